// round 6
// baseline (speedup 1.0000x reference)
#include <cuda_runtime.h>

// EnergyModel: energy[t] = sum_q qa[q] * sum_f w[f]*(desc[t,q,f]-qf[t,q,f])^2
// with range masking on T[:,4:7]. HBM-bound streaming reduction.
//
// R6: mask-compacted work distribution. A resident grid (740 CTAs) first
// builds the dense list of ACTIVE rows (ballot + block prefix scan over the
// 1024-row mask), then grid-strides over active (row, chunk) pairs only:
// ~2608 live chunks / 740 CTAs = near-perfect deterministic balance, no dead
// CTAs, per-CTA setup done once. Row partials folded by last-arriving CTA
// (fixed-order sum -> deterministic).

#define NQ 128
#define FDIM 576                    // 64*1 + 64*3 + 64*5
#define NGRP 192
#define SPLIT 8
#define QPC (NQ / SPLIT)            // 16 queries per chunk
#define THREADS 256
#define F4_PER_ROW (FDIM / 4)       // 144
#define F4_TOTAL (NQ * F4_PER_ROW)  // 18432 float4 per t per tensor
#define CHUNK_F4 (QPC * F4_PER_ROW) // 2304 float4 per chunk per tensor
#define NT_MAX 1024
#define GRID 740                    // 5 CTAs/SM x 148 SMs

__device__ float g_partial[NT_MAX * SPLIT];
__device__ int   g_count[NT_MAX];    // zero-init; folding CTA resets to 0

__global__ void __launch_bounds__(THREADS, 5)
energy_kernel(const float* __restrict__ T,
              const float4* __restrict__ desc,
              const float4* __restrict__ qf,
              const float* __restrict__ qa,
              const float* __restrict__ logit,
              const float* __restrict__ ranges,
              float* __restrict__ out,
              int nt)
{
    const int tid  = threadIdx.x;
    const int bid  = blockIdx.x;
    const int lane = tid & 31;
    const int wid  = tid >> 5;

    __shared__ unsigned short s_list[NT_MAX];   // dense active row ids
    __shared__ float s_w[FDIM];                 // per-feature weights (16B-aligned)
    __shared__ float s_qa[NQ];
    __shared__ float s_red[THREADS / 32];
    __shared__ int   s_wsum[THREADS / 32];
    __shared__ int   s_nact;

    // ---- Phase 1: mask scan -> dense active-row list (every CTA, identical).
    const float r0lo = ranges[0], r0hi = ranges[1];
    const float r1lo = ranges[2], r1hi = ranges[3];
    const float r2lo = ranges[4], r2hi = ranges[5];

    bool m[4];
    int cnt = 0;
    const int rbase = tid * 4;
    #pragma unroll
    for (int k = 0; k < 4; k++) {
        const int row = rbase + k;
        bool ok = false;
        if (row < nt) {
            const float x0 = T[row * 7 + 4];
            const float x1 = T[row * 7 + 5];
            const float x2 = T[row * 7 + 6];
            ok = (r0hi >= x0) && (x0 >= r0lo) &&
                 (r1hi >= x1) && (x1 >= r1lo) &&
                 (r2hi >= x2) && (x2 >= r2lo);
            if (!ok && bid == 0) out[row] = 100000.0f;   // masked rows
        }
        m[k] = ok;
        cnt += ok ? 1 : 0;
    }
    // warp inclusive scan of cnt
    int incl = cnt;
    #pragma unroll
    for (int o = 1; o < 32; o <<= 1) {
        const int v = __shfl_up_sync(0xffffffffu, incl, o);
        if (lane >= o) incl += v;
    }
    if (lane == 31) s_wsum[wid] = incl;
    __syncthreads();
    int wbase = 0;
    #pragma unroll
    for (int w = 0; w < THREADS / 32; w++)
        if (w < wid) wbase += s_wsum[w];
    int pos = wbase + (incl - cnt);
    #pragma unroll
    for (int k = 0; k < 4; k++)
        if (m[k]) s_list[pos++] = (unsigned short)(rbase + k);
    if (tid == THREADS - 1) s_nact = wbase + incl;

    // ---- Phase 2: per-CTA setup (once): weights + attention to shared.
    const float scale = 2.0f / (0.6931471805599453f * (float)NGRP);
    __shared__ float s_g[NGRP];
    if (tid < NGRP) {
        const float x = logit[tid];
        s_g[tid] = (fmaxf(x, 0.0f) + log1pf(expf(-fabsf(x)))) * scale;
    }
    if (tid < NQ) s_qa[tid] = qa[tid];
    __syncthreads();
    for (int f = tid; f < FDIM; f += THREADS) {
        int g;
        if (f < 64)        g = f;                    // l=0, d=1
        else if (f < 256)  g = 64 + (f - 64) / 3;    // l=1, d=3
        else               g = 128 + (f - 256) / 5;  // l=2, d=5
        s_w[f] = s_g[g];
    }
    __syncthreads();

    const int nact    = s_nact;
    const int nchunks = nact * SPLIT;
    const float4* s_w4 = (const float4*)s_w;

    // ---- Phase 3: grid-stride over ACTIVE chunks only.
    for (int idx = bid; idx < nchunks; idx += GRID) {
        const int a = idx >> 3;               // SPLIT == 8
        const int c = idx & (SPLIT - 1);
        const int t = s_list[a];

        const float4* db = desc + (size_t)t * F4_TOTAL + (size_t)c * CHUNK_F4;
        const float4* qb = qf   + (size_t)t * F4_TOTAL + (size_t)c * CHUNK_F4;
        const float*  qac = &s_qa[c * QPC];

        float acc = 0.0f;
        #pragma unroll 3
        for (int j = tid; j < CHUNK_F4; j += THREADS) {   // 9 iterations
            const int q  = j / F4_PER_ROW;
            const int f4 = j - q * F4_PER_ROW;
            const float4 d = __ldcs(db + j);
            const float4 e = __ldcs(qb + j);
            const float4 w = s_w4[f4];
            const float dx = d.x - e.x;
            const float dy = d.y - e.y;
            const float dz = d.z - e.z;
            const float dw = d.w - e.w;
            float s = w.x * dx * dx;
            s = fmaf(w.y, dy * dy, s);
            s = fmaf(w.z, dz * dz, s);
            s = fmaf(w.w, dw * dw, s);
            acc = fmaf(qac[q], s, acc);
        }

        // block reduction (8 warps)
        #pragma unroll
        for (int o = 16; o > 0; o >>= 1)
            acc += __shfl_down_sync(0xffffffffu, acc, o);
        if (lane == 0) s_red[wid] = acc;
        __syncthreads();

        if (tid == 0) {
            float v = 0.0f;
            #pragma unroll
            for (int w = 0; w < THREADS / 32; w++) v += s_red[w];
            g_partial[t * SPLIT + c] = v;
            __threadfence();                  // publish partial before count
            const int prev = atomicAdd(&g_count[t], 1);
            if (prev == SPLIT - 1) {
                __threadfence();              // acquire peer partials
                const float* gp = &g_partial[t * SPLIT];
                float s = 0.0f;
                #pragma unroll
                for (int i = 0; i < SPLIT; i++)
                    s += __ldcg(&gp[i]);
                out[t] = s;
                g_count[t] = 0;               // reset for next graph replay
            }
        }
        __syncthreads();                      // protect s_red reuse
    }
}

extern "C" void kernel_launch(void* const* d_in, const int* in_sizes, int n_in,
                              void* d_out, int out_size)
{
    const float*  T      = (const float*)d_in[0];
    const float4* desc   = (const float4*)d_in[1];
    const float4* qf     = (const float4*)d_in[2];
    const float*  qa     = (const float*)d_in[3];
    const float*  logit  = (const float*)d_in[4];
    const float*  ranges = (const float*)d_in[5];
    float* out = (float*)d_out;

    const int nt = in_sizes[0] / 7;   // 1024

    energy_kernel<<<GRID, THREADS>>>(T, desc, qf, qa, logit, ranges, out, nt);
}

// round 7
// speedup vs baseline: 1.1089x; 1.1089x over previous
#include <cuda_runtime.h>

// EnergyModel: energy[t] = sum_q qa[q] * sum_f w[f]*(desc[t,q,f]-qf[t,q,f])^2
// with range masking on T[:,4:7]. HBM-bound streaming reduction.
//
// R7: R2's two-kernel structure (best measured streaming rate) with
//  (a) batched loads — 3 batches of 3 float4-pairs issued before compute,
//      raising per-warp MLP from ~2 to 6 (R1/R2 were latency-limited at
//      ~5 TB/s achieved HBM, not imbalance-limited: R6 proved balance
//      doesn't help), and
//  (b) a parallel finalize (8x128, float4 folds) replacing R2's 5us
//      latency-bound grid=4 finalize.
// No atomics/fences in the hot path (R5 showed the in-kernel fold costs
// ~5us of streaming rate).

#define NQ 128
#define FDIM 576                    // 64*1 + 64*3 + 64*5
#define NGRP 192
#define SPLIT 8
#define QPC (NQ / SPLIT)            // 16 queries per chunk
#define THREADS 256
#define F4_PER_ROW (FDIM / 4)       // 144
#define F4_TOTAL (NQ * F4_PER_ROW)  // 18432 float4 per t per tensor
#define CHUNK_F4 (QPC * F4_PER_ROW) // 2304 float4 per chunk per tensor
#define NT_MAX 1024
#define NBATCH 3
#define UB 3                        // loads batched per phase

__device__ float g_partial[NT_MAX * SPLIT];

__global__ void __launch_bounds__(THREADS)
partial_kernel(const float* __restrict__ T,
               const float4* __restrict__ desc,
               const float4* __restrict__ qf,
               const float* __restrict__ qa,
               const float* __restrict__ logit,
               const float* __restrict__ ranges)
{
    const int bx  = blockIdx.x;
    const int t   = bx >> 3;             // SPLIT == 8
    const int c   = bx & (SPLIT - 1);
    const int tid = threadIdx.x;

    // Range mask: uniform predicate; dead CTAs retire without touching payload.
    {
        const float x0 = T[t * 7 + 4];
        const float x1 = T[t * 7 + 5];
        const float x2 = T[t * 7 + 6];
        const bool ok = (ranges[1] >= x0) && (x0 >= ranges[0]) &&
                        (ranges[3] >= x1) && (x1 >= ranges[2]) &&
                        (ranges[5] >= x2) && (x2 >= ranges[4]);
        if (!ok) return;
    }

    __shared__ float s_g[NGRP];
    __shared__ float s_w[FDIM];
    __shared__ float s_qa[QPC];
    __shared__ float s_red[THREADS / 32];

    // Weight setup: 192 softplus -> expand to 576 per-feature weights (LDS only).
    const float scale = 2.0f / (0.6931471805599453f * (float)NGRP);
    if (tid < NGRP) {
        const float x = logit[tid];
        s_g[tid] = (fmaxf(x, 0.0f) + log1pf(expf(-fabsf(x)))) * scale;
    }
    if (tid < QPC) s_qa[tid] = qa[c * QPC + tid];
    __syncthreads();
    for (int f = tid; f < FDIM; f += THREADS) {
        int g;
        if (f < 64)        g = f;                    // l=0, d=1
        else if (f < 256)  g = 64 + (f - 64) / 3;    // l=1, d=3
        else               g = 128 + (f - 256) / 5;  // l=2, d=5
        s_w[f] = s_g[g];
    }
    __syncthreads();

    const float4* db = desc + (size_t)t * F4_TOTAL + (size_t)c * CHUNK_F4;
    const float4* qb = qf   + (size_t)t * F4_TOTAL + (size_t)c * CHUNK_F4;
    const float4* s_w4 = (const float4*)s_w;

    float acc = 0.0f;
    #pragma unroll
    for (int b = 0; b < NBATCH; b++) {
        float4 dv[UB], ev[UB];
        // Phase 1: issue all 6 independent loads (MLP_p1 = 6).
        #pragma unroll
        for (int u = 0; u < UB; u++) {
            const int j = tid + (b * UB + u) * THREADS;
            dv[u] = db[j];
            ev[u] = qb[j];
        }
        // Phase 2: consume.
        #pragma unroll
        for (int u = 0; u < UB; u++) {
            const int j  = tid + (b * UB + u) * THREADS;
            const int q  = j / F4_PER_ROW;
            const int f4 = j - q * F4_PER_ROW;
            const float4 w = s_w4[f4];
            const float dx = dv[u].x - ev[u].x;
            const float dy = dv[u].y - ev[u].y;
            const float dz = dv[u].z - ev[u].z;
            const float dw = dv[u].w - ev[u].w;
            float s = w.x * dx * dx;
            s = fmaf(w.y, dy * dy, s);
            s = fmaf(w.z, dz * dz, s);
            s = fmaf(w.w, dw * dw, s);
            acc = fmaf(s_qa[q], s, acc);
        }
    }

    // Block reduction (8 warps).
    #pragma unroll
    for (int o = 16; o > 0; o >>= 1)
        acc += __shfl_down_sync(0xffffffffu, acc, o);
    if ((tid & 31) == 0) s_red[tid >> 5] = acc;
    __syncthreads();
    if (tid == 0) {
        float v = 0.0f;
        #pragma unroll
        for (int w = 0; w < THREADS / 32; w++) v += s_red[w];
        g_partial[bx] = v;
    }
}

__global__ void __launch_bounds__(128)
finalize_kernel(const float* __restrict__ T,
                const float* __restrict__ ranges,
                float* __restrict__ out,
                int nt)
{
    const int t = blockIdx.x * blockDim.x + threadIdx.x;
    if (t >= nt) return;

    const float x0 = T[t * 7 + 4];
    const float x1 = T[t * 7 + 5];
    const float x2 = T[t * 7 + 6];
    const bool ok = (ranges[1] >= x0) && (x0 >= ranges[0]) &&
                    (ranges[3] >= x1) && (x1 >= ranges[2]) &&
                    (ranges[5] >= x2) && (x2 >= ranges[4]);
    if (!ok) {
        out[t] = 100000.0f;
        return;
    }
    // 8 contiguous partials = 2 x float4 (fixed-order fold: deterministic).
    const float4* gp = (const float4*)&g_partial[t * SPLIT];
    const float4 a = gp[0];
    const float4 b = gp[1];
    out[t] = ((a.x + a.y) + (a.z + a.w)) + ((b.x + b.y) + (b.z + b.w));
}

extern "C" void kernel_launch(void* const* d_in, const int* in_sizes, int n_in,
                              void* d_out, int out_size)
{
    const float*  T      = (const float*)d_in[0];
    const float4* desc   = (const float4*)d_in[1];
    const float4* qf     = (const float4*)d_in[2];
    const float*  qa     = (const float*)d_in[3];
    const float*  logit  = (const float*)d_in[4];
    const float*  ranges = (const float*)d_in[5];
    float* out = (float*)d_out;

    const int nt = in_sizes[0] / 7;   // 1024

    partial_kernel<<<nt * SPLIT, THREADS>>>(T, desc, qf, qa, logit, ranges);
    finalize_kernel<<<(nt + 127) / 128, 128>>>(T, ranges, out, nt);
}

// round 8
// speedup vs baseline: 1.1803x; 1.0643x over previous
#include <cuda_runtime.h>

// EnergyModel: energy[t] = sum_q qa[q] * sum_f w[f]*(desc[t,q,f]-qf[t,q,f])^2
// with range masking on T[:,4:7]. HBM-bound streaming reduction.
//
// R8: R7's partial kernel unchanged (measured 32.5us = 5.9TB/s: batched
// 3x3 float4-pair loads, SPLIT=8 x 256thr). The 5.1us finalize was shown to
// be size-invariant launch/prologue latency -> overlap it with PDL:
// primary triggers programmatic launch at CTA start; finalize does all
// partial-independent work (mask, masked-row writes) before
// cudaGridDependencySynchronize(), leaving only an L2 read + store exposed.

#define NQ 128
#define FDIM 576                    // 64*1 + 64*3 + 64*5
#define NGRP 192
#define SPLIT 8
#define QPC (NQ / SPLIT)            // 16 queries per chunk
#define THREADS 256
#define F4_PER_ROW (FDIM / 4)       // 144
#define F4_TOTAL (NQ * F4_PER_ROW)  // 18432 float4 per t per tensor
#define CHUNK_F4 (QPC * F4_PER_ROW) // 2304 float4 per chunk per tensor
#define NT_MAX 1024
#define NBATCH 3
#define UB 3                        // float4-pairs batched per phase (MLP=6)

__device__ float g_partial[NT_MAX * SPLIT];

__global__ void __launch_bounds__(THREADS)
partial_kernel(const float* __restrict__ T,
               const float4* __restrict__ desc,
               const float4* __restrict__ qf,
               const float* __restrict__ qa,
               const float* __restrict__ logit,
               const float* __restrict__ ranges)
{
    // Let the finalize kernel launch immediately; it self-synchronizes via
    // cudaGridDependencySynchronize before consuming g_partial.
    cudaTriggerProgrammaticLaunchCompletion();

    const int bx  = blockIdx.x;
    const int t   = bx >> 3;             // SPLIT == 8
    const int c   = bx & (SPLIT - 1);
    const int tid = threadIdx.x;

    // Range mask: uniform predicate; dead CTAs retire without touching payload.
    {
        const float x0 = T[t * 7 + 4];
        const float x1 = T[t * 7 + 5];
        const float x2 = T[t * 7 + 6];
        const bool ok = (ranges[1] >= x0) && (x0 >= ranges[0]) &&
                        (ranges[3] >= x1) && (x1 >= ranges[2]) &&
                        (ranges[5] >= x2) && (x2 >= ranges[4]);
        if (!ok) return;
    }

    __shared__ float s_g[NGRP];
    __shared__ float s_w[FDIM];
    __shared__ float s_qa[QPC];
    __shared__ float s_red[THREADS / 32];

    // Weight setup: 192 softplus -> expand to 576 per-feature weights (LDS only).
    const float scale = 2.0f / (0.6931471805599453f * (float)NGRP);
    if (tid < NGRP) {
        const float x = logit[tid];
        s_g[tid] = (fmaxf(x, 0.0f) + log1pf(expf(-fabsf(x)))) * scale;
    }
    if (tid < QPC) s_qa[tid] = qa[c * QPC + tid];
    __syncthreads();
    for (int f = tid; f < FDIM; f += THREADS) {
        int g;
        if (f < 64)        g = f;                    // l=0, d=1
        else if (f < 256)  g = 64 + (f - 64) / 3;    // l=1, d=3
        else               g = 128 + (f - 256) / 5;  // l=2, d=5
        s_w[f] = s_g[g];
    }
    __syncthreads();

    const float4* db = desc + (size_t)t * F4_TOTAL + (size_t)c * CHUNK_F4;
    const float4* qb = qf   + (size_t)t * F4_TOTAL + (size_t)c * CHUNK_F4;
    const float4* s_w4 = (const float4*)s_w;

    float acc = 0.0f;
    #pragma unroll
    for (int b = 0; b < NBATCH; b++) {
        float4 dv[UB], ev[UB];
        // Phase 1: issue all 6 independent loads (MLP_p1 = 6).
        #pragma unroll
        for (int u = 0; u < UB; u++) {
            const int j = tid + (b * UB + u) * THREADS;
            dv[u] = db[j];
            ev[u] = qb[j];
        }
        // Phase 2: consume.
        #pragma unroll
        for (int u = 0; u < UB; u++) {
            const int j  = tid + (b * UB + u) * THREADS;
            const int q  = j / F4_PER_ROW;
            const int f4 = j - q * F4_PER_ROW;
            const float4 w = s_w4[f4];
            const float dx = dv[u].x - ev[u].x;
            const float dy = dv[u].y - ev[u].y;
            const float dz = dv[u].z - ev[u].z;
            const float dw = dv[u].w - ev[u].w;
            float s = w.x * dx * dx;
            s = fmaf(w.y, dy * dy, s);
            s = fmaf(w.z, dz * dz, s);
            s = fmaf(w.w, dw * dw, s);
            acc = fmaf(s_qa[q], s, acc);
        }
    }

    // Block reduction (8 warps).
    #pragma unroll
    for (int o = 16; o > 0; o >>= 1)
        acc += __shfl_down_sync(0xffffffffu, acc, o);
    if ((tid & 31) == 0) s_red[tid >> 5] = acc;
    __syncthreads();
    if (tid == 0) {
        float v = 0.0f;
        #pragma unroll
        for (int w = 0; w < THREADS / 32; w++) v += s_red[w];
        g_partial[bx] = v;
    }
}

__global__ void __launch_bounds__(128)
finalize_kernel(const float* __restrict__ T,
                const float* __restrict__ ranges,
                float* __restrict__ out,
                int nt)
{
    const int t = blockIdx.x * blockDim.x + threadIdx.x;

    // ---- Prologue: everything independent of g_partial (overlaps primary).
    bool ok = false;
    if (t < nt) {
        const float x0 = T[t * 7 + 4];
        const float x1 = T[t * 7 + 5];
        const float x2 = T[t * 7 + 6];
        ok = (ranges[1] >= x0) && (x0 >= ranges[0]) &&
             (ranges[3] >= x1) && (x1 >= ranges[2]) &&
             (ranges[5] >= x2) && (x2 >= ranges[4]);
        if (!ok) out[t] = 100000.0f;     // masked rows: no dependency
    }
    if (!ok) return;                      // exit before the dependency sync

    // ---- Wait for the primary grid's writes to become visible.
    cudaGridDependencySynchronize();

    // 8 contiguous partials = 2 x float4 (fixed-order fold: deterministic).
    const float4* gp = (const float4*)&g_partial[t * SPLIT];
    const float4 a = gp[0];
    const float4 b = gp[1];
    out[t] = ((a.x + a.y) + (a.z + a.w)) + ((b.x + b.y) + (b.z + b.w));
}

extern "C" void kernel_launch(void* const* d_in, const int* in_sizes, int n_in,
                              void* d_out, int out_size)
{
    const float*  T      = (const float*)d_in[0];
    const float4* desc   = (const float4*)d_in[1];
    const float4* qf     = (const float4*)d_in[2];
    const float*  qa     = (const float*)d_in[3];
    const float*  logit  = (const float*)d_in[4];
    const float*  ranges = (const float*)d_in[5];
    float* out = (float*)d_out;

    const int nt = in_sizes[0] / 7;   // 1024

    partial_kernel<<<nt * SPLIT, THREADS>>>(T, desc, qf, qa, logit, ranges);

    // Finalize with Programmatic Stream Serialization: launches as soon as
    // all primary CTAs have triggered, overlapping its prologue with the
    // primary's tail.
    cudaLaunchConfig_t cfg = {};
    cfg.gridDim  = dim3((nt + 127) / 128);
    cfg.blockDim = dim3(128);
    cfg.dynamicSmemBytes = 0;
    cfg.stream = 0;
    cudaLaunchAttribute attrs[1];
    attrs[0].id = cudaLaunchAttributeProgrammaticStreamSerialization;
    attrs[0].val.programmaticStreamSerializationAllowed = 1;
    cfg.attrs = attrs;
    cfg.numAttrs = 1;
    cudaLaunchKernelEx(&cfg, finalize_kernel, T, ranges, out, nt);
}